// round 5
// baseline (speedup 1.0000x reference)
#include <cuda_runtime.h>
#include <cstdint>

typedef unsigned long long ull;

// ---------------------------------------------------------------------------
// Shapes
// ---------------------------------------------------------------------------
#define BB    256            // batch
#define LL    256            // seq len
#define HH    128            // pooled len
#define VV    14             // vocab
#define NP    196            // 14*14 ordered pairs
#define EMBD  512
#define OC    256            // branch conv out channels
#define NJ    128            // branch linear out
#define KDIM  32768          // OC*HH
#define ZROW  (3*NP)         // zero row index in g_G (conv padding taps)
// GEMM: grid 128 blocks x 512 threads; block = (all 256 rows) x 128 n x KC=256
#define KSPLIT 128
#define KC     256           // = OC, exactly one pooled position h per block
#define GKT    16
#define NSTG   (KC / GKT)    // 16
#define GM     256
#define GN     128

// dynamic smem layout for gemm
#define YS_BYTES   (2 * 256 * 18 * 8)          // ull Ys2[2][256][18] = 73728
#define WS_OFF     YS_BYTES
#define WS_BYTES   (2 * 16 * 128 * 4)          // float Ws[2][16][128] = 16384
#define SIDX_OFF   (WS_OFF + WS_BYTES)         // 90112
#define SIDX_BYTES (3 * 256 * 4)               // int sidx[3][256] = 3072
#define CBS_OFF    (SIDX_OFF + SIDX_BYTES)     // 93184
#define GEMM_SMEM  (CBS_OFF + 256 * 4)         // 94208

// ---------------------------------------------------------------------------
// Scratch
// ---------------------------------------------------------------------------
__device__ float g_ME[2 * NP * EMBD];            // pair-max embedding tables
__device__ float g_Wt[3 * EMBD * OC];            // conv kw=1 slice, [kh][c][o]
__device__ float g_G[(3 * NP + 1) * OC];         // G[kh][pair][o] + zero row
__device__ int   g_Ppad[BB * 130];               // pair ids, h' in [-1,128]
__device__ float g_part[(size_t)KSPLIT * BB * NJ];
__device__ float g_MW[3 * 64 * 128];             // manip combined conv weights
__device__ float g_A[3 * 64 * 256];              // manip reduced linear weights
__device__ int   g_tok[BB * 256];                // friend tokens

// ---------------------------------------------------------------------------
// packed f32x2 helpers + Kahan
// ---------------------------------------------------------------------------
__device__ __forceinline__ ull pk2(float x, float y) {
    ull r; asm("mov.b64 %0, {%1,%2};" : "=l"(r) : "f"(x), "f"(y)); return r;
}
__device__ __forceinline__ ull fma2(ull a, ull b, ull c) {
    ull d; asm("fma.rn.f32x2 %0, %1, %2, %3;" : "=l"(d) : "l"(a), "l"(b), "l"(c));
    return d;
}
__device__ __forceinline__ void upk2(ull v, float& x, float& y) {
    asm("mov.b64 {%0,%1}, %2;" : "=f"(x), "=f"(y) : "l"(v));
}
__device__ __forceinline__ void kadd(float& s, float& c, float x) {
    float y = __fadd_rn(x, -c);
    float t = __fadd_rn(s, y);
    c = __fadd_rn(__fadd_rn(t, -s), -y);
    s = t;
}

// ---------------------------------------------------------------------------
// Prep kernels
// ---------------------------------------------------------------------------
__global__ void me_kernel(const float* __restrict__ emb, int slot) {
    int p = blockIdx.x, c = threadIdx.x;
    int t0 = p / VV, t1 = p % VV;
    g_ME[slot * NP * EMBD + p * EMBD + c] =
        fmaxf(emb[t0 * EMBD + c], emb[t1 * EMBD + c]);
}

// coalesced conv-slice transpose + pair-id table + zero G row.
// One block per output channel o (=256 blocks); also block b handles Ppad[b].
__global__ void __launch_bounds__(256) wt_kernel(const float* __restrict__ w,
                                                 const int* __restrict__ xt,
                                                 int use_tok) {
    __shared__ float sw[4608];                  // one o-slab: 512 c x 9 taps
    int o = blockIdx.x, tid = threadIdx.x;
#pragma unroll
    for (int i = 0; i < 18; i++)
        sw[i * 256 + tid] = w[(size_t)o * 4608 + i * 256 + tid];
    __syncthreads();
    for (int i = tid; i < 1536; i += 256) {
        int c = i & 511, kh = i >> 9;
        g_Wt[(kh * EMBD + c) * OC + o] = sw[c * 9 + kh * 3 + 1];
    }
    if (o == 0) g_G[ZROW * OC + tid] = 0.f;
    {   // pair-id table for batch row b = blockIdx.x
        int b = blockIdx.x;
        const int* tb = (use_tok ? g_tok : xt) + b * LL;
        if (tid < 130) {
            int hp = tid - 1;                   // h' in [-1,128]
            int p = -1;
            if (hp >= 0 && hp < HH) p = tb[2 * hp] * VV + tb[2 * hp + 1];
            g_Ppad[b * 130 + tid] = p;
        }
    }
}

// G[kh][p][o] = sum_c ME[p][c] * Wt[kh][c][o];  FFMA2 over pair-pairs
__global__ void __launch_bounds__(128) G_kernel(int slot) {
    int pg = blockIdx.x;                 // 0..13
    int kh = blockIdx.y;                 // 0..2
    int o  = blockIdx.z * 128 + threadIdx.x;
    int t  = threadIdx.x;
    __shared__ ull sME2[7][128];
    ull acc[7];
#pragma unroll
    for (int i = 0; i < 7; i++) acc[i] = 0ull;
    const float* ME = g_ME + slot * NP * EMBD;
    for (int cc = 0; cc < EMBD; cc += 128) {
#pragma unroll
        for (int i = 0; i < 7; i++)
            sME2[i][t] = pk2(ME[(pg * 14 + 2 * i) * EMBD + cc + t],
                             ME[(pg * 14 + 2 * i + 1) * EMBD + cc + t]);
        __syncthreads();
#pragma unroll 4
        for (int c2 = 0; c2 < 128; c2++) {
            float wv = g_Wt[(kh * EMBD + cc + c2) * OC + o];
            ull pw = pk2(wv, wv);
#pragma unroll
            for (int i = 0; i < 7; i++) acc[i] = fma2(pw, sME2[i][c2], acc[i]);
        }
        __syncthreads();
    }
#pragma unroll
    for (int i = 0; i < 7; i++) {
        float lo, hi; upk2(acc[i], lo, hi);
        g_G[(kh * NP + pg * 14 + 2 * i) * OC + o]     = lo;
        g_G[(kh * NP + pg * 14 + 2 * i + 1) * OC + o] = hi;
    }
}

// ---------------------------------------------------------------------------
// Fused GEMM: partial C[256,128] over one pooled position h = blockIdx.x.
// Y rows computed in-staging from 3 gathered G rows + bias; W read directly
// from Wl with permuted indexing. 512 threads, 8m x (4x2n) thread tile, FFMA2.
// ---------------------------------------------------------------------------
__global__ void __launch_bounds__(512) gemm_kernel(const float* __restrict__ cb,
                                                   const float* __restrict__ Wl) {
    extern __shared__ char sm[];
    ull   (*Ys2)[256][18] = (ull(*)[256][18])sm;
    float (*Ws)[16][128]  = (float(*)[16][128])(sm + WS_OFF);
    int   (*sidx)[256]    = (int(*)[256])(sm + SIDX_OFF);
    float* cbs            = (float*)(sm + CBS_OFF);

    int h  = blockIdx.x;                  // 0..127 (= k-split id)
    int tid = threadIdx.x;

    if (tid < 256) cbs[tid] = cb[tid];
    for (int q = tid; q < 768; q += 512) {
        int t = q >> 8, r = q & 255;
        int hp = h - 1 + t;                                // [-1,128]
        int p = g_Ppad[r * 130 + hp + 1];
        sidx[t][r] = (p < 0) ? ZROW : t * NP + p;
    }
    __syncthreads();

    int yr0 = tid >> 2, yc = (tid & 3) * 4;                // + i*128 rows
    int wr  = tid >> 5, wc = (tid & 31) * 4;               // one f4 per thread
    int nt = tid & 15, mt = tid >> 4, m0 = mt * 8;

    float4 vy[2], vw;

    // stage 0
    {
#pragma unroll
        for (int i = 0; i < 2; i++) {
            int r = yr0 + i * 128;
            const float4 g0 = *(const float4*)&g_G[sidx[0][r] * OC + yc];
            const float4 g1 = *(const float4*)&g_G[sidx[1][r] * OC + yc];
            const float4 g2 = *(const float4*)&g_G[sidx[2][r] * OC + yc];
            const float4 bi = *(const float4*)&cbs[yc];
            vy[i].x = bi.x + g0.x + g1.x + g2.x;
            vy[i].y = bi.y + g0.y + g1.y + g2.y;
            vy[i].z = bi.z + g0.z + g1.z + g2.z;
            vy[i].w = bi.w + g0.w + g1.w + g2.w;
        }
        vw = *(const float4*)&Wl[(size_t)(wr * HH + h) * NJ + wc];
#pragma unroll
        for (int i = 0; i < 2; i++) {
            int r = yr0 + i * 128;
            Ys2[0][r][yc + 0] = pk2(vy[i].x, vy[i].x);
            Ys2[0][r][yc + 1] = pk2(vy[i].y, vy[i].y);
            Ys2[0][r][yc + 2] = pk2(vy[i].z, vy[i].z);
            Ys2[0][r][yc + 3] = pk2(vy[i].w, vy[i].w);
        }
        *(float4*)&Ws[0][wr][wc] = vw;
    }
    __syncthreads();

    ull acc[8][4];
#pragma unroll
    for (int i = 0; i < 8; i++)
#pragma unroll
        for (int k = 0; k < 4; k++) acc[i][k] = 0ull;

#pragma unroll 1
    for (int s = 0; s < NSTG; s++) {
        int buf = s & 1;
        if (s + 1 < NSTG) {
            int o0 = (s + 1) << 4;
#pragma unroll
            for (int i = 0; i < 2; i++) {
                int r = yr0 + i * 128;
                const float4 g0 = *(const float4*)&g_G[sidx[0][r] * OC + o0 + yc];
                const float4 g1 = *(const float4*)&g_G[sidx[1][r] * OC + o0 + yc];
                const float4 g2 = *(const float4*)&g_G[sidx[2][r] * OC + o0 + yc];
                const float4 bi = *(const float4*)&cbs[o0 + yc];
                vy[i].x = bi.x + g0.x + g1.x + g2.x;
                vy[i].y = bi.y + g0.y + g1.y + g2.y;
                vy[i].z = bi.z + g0.z + g1.z + g2.z;
                vy[i].w = bi.w + g0.w + g1.w + g2.w;
            }
            vw = *(const float4*)&Wl[(size_t)((o0 + wr) * HH + h) * NJ + wc];
        }
#pragma unroll
        for (int kk = 0; kk < GKT; kk++) {
            ull bb[4];
#pragma unroll
            for (int k = 0; k < 4; k++)
                bb[k] = *(const ull*)&Ws[buf][kk][nt * 2 + k * 32];
#pragma unroll
            for (int i = 0; i < 8; i++) {
                ull ya = Ys2[buf][m0 + i][kk];
#pragma unroll
                for (int k = 0; k < 4; k++)
                    acc[i][k] = fma2(ya, bb[k], acc[i][k]);
            }
        }
        if (s + 1 < NSTG) {
            int nb = buf ^ 1;
#pragma unroll
            for (int i = 0; i < 2; i++) {
                int r = yr0 + i * 128;
                Ys2[nb][r][yc + 0] = pk2(vy[i].x, vy[i].x);
                Ys2[nb][r][yc + 1] = pk2(vy[i].y, vy[i].y);
                Ys2[nb][r][yc + 2] = pk2(vy[i].z, vy[i].z);
                Ys2[nb][r][yc + 3] = pk2(vy[i].w, vy[i].w);
            }
            *(float4*)&Ws[nb][wr][wc] = vw;
        }
        __syncthreads();
    }

    float* P = g_part + (size_t)h * BB * GN;
#pragma unroll
    for (int i = 0; i < 8; i++)
#pragma unroll
        for (int k = 0; k < 4; k++)
            *(ull*)&P[(size_t)(m0 + i) * GN + nt * 2 + k * 32] = acc[i][k];
}

// ---------------------------------------------------------------------------
// prep2: fused manip conv-weight collapse (blocks 0..31) + reduced linear
// prefix sums with 4 parallel Kahan chains (blocks 32..95)
// ---------------------------------------------------------------------------
__global__ void __launch_bounds__(256) prep2_kernel(const float* __restrict__ mcw,
                                                    const float* __restrict__ mlw) {
    int blk = blockIdx.x, tid = threadIdx.x;
    if (blk < 32) {
        int idx = blk * 256 + tid;               // 8192
        int base = idx * 9 + 1;
        float w0 = mcw[base], w1 = mcw[base + 3], w2 = mcw[base + 6];
        g_MW[0 * 8192 + idx] = w1 + w2;
        g_MW[1 * 8192 + idx] = w0 + w1 + w2;
        g_MW[2 * 8192 + idx] = w0 + w1;
    } else {
        int o = blk - 32;                        // 0..63
        int j = tid;                             // 0..255
        const float* base = mlw + (size_t)(o * 128) * 256 + j;
        g_A[0 * 16384 + o * 256 + j] = base[0];
        g_A[2 * 16384 + o * 256 + j] = base[127 * 256];
        float s0 = 0, c0 = 0, s1 = 0, c1 = 0, s2 = 0, c2 = 0, s3 = 0, c3 = 0;
#pragma unroll 4
        for (int h = 1; h < 32; h++)   kadd(s0, c0, base[h * 256]);
#pragma unroll 4
        for (int h = 32; h < 64; h++)  kadd(s1, c1, base[h * 256]);
#pragma unroll 4
        for (int h = 64; h < 96; h++)  kadd(s2, c2, base[h * 256]);
#pragma unroll 4
        for (int h = 96; h < 127; h++) kadd(s3, c3, base[h * 256]);
        float a = __fadd_rn(__fadd_rn(__fadd_rn(s0, c0), __fadd_rn(s1, c1)),
                            __fadd_rn(__fadd_rn(s2, c2), __fadd_rn(s3, c3)));
        g_A[1 * 16384 + o * 256 + j] = a;
    }
}

// ---------------------------------------------------------------------------
// Manipulator fused: split-K reduce + softmax + collapsed conv/linear + tokens
// ---------------------------------------------------------------------------
__global__ void __launch_bounds__(256) manip_kernel(const float* __restrict__ elb,
                                                    const float* __restrict__ mcb,
                                                    const float* __restrict__ mlb) {
    int b = blockIdx.x, tid = threadIdx.x;
    __shared__ float seo[128];
    __shared__ float sr[192];
    __shared__ float s[128];
    float v = 0.f;
    if (tid < 128) {                             // split-K reduce (Kahan)
        float ks = 0.f, kc = 0.f;
        const float* p = g_part + (size_t)b * NJ + tid;
#pragma unroll 8
        for (int k = 0; k < KSPLIT; k++) kadd(ks, kc, p[(size_t)k * BB * NJ]);
        v = __fadd_rn(elb[tid], __fadd_rn(ks, kc));
        s[tid] = v;
    }
    __syncthreads();
    for (int st = 64; st > 0; st >>= 1) {
        if (tid < st) s[tid] = fmaxf(s[tid], s[tid + st]);
        __syncthreads();
    }
    float mx = s[0];
    __syncthreads();
    float e = 0.f;
    if (tid < 128) { e = expf(v - mx); s[tid] = e; }
    __syncthreads();
    for (int st = 64; st > 0; st >>= 1) {
        if (tid < st) s[tid] += s[tid + st];
        __syncthreads();
    }
    if (tid < 128) seo[tid] = e / s[0];
    __syncthreads();
    if (tid < 192) {                             // 3 conv-row dots (Kahan)
        int o = tid % 64;
        float ks = 0.f, kc = 0.f;
        const float* Wr = g_MW + (tid / 64) * 8192 + o * 128;
#pragma unroll 8
        for (int c = 0; c < 128; c++) kadd(ks, kc, __fmul_rn(seo[c], Wr[c]));
        sr[tid] = fmaxf(__fadd_rn(mcb[o], __fadd_rn(ks, kc)), 0.f);
    }
    __syncthreads();
    {                                            // reduced linear (Kahan)
        int j = tid;
        float ks = 0.f, kc = 0.f;
#pragma unroll 8
        for (int q = 0; q < 192; q++)
            kadd(ks, kc, __fmul_rn(sr[q], g_A[q * 256 + j]));
        float m = __fadd_rn(mlb[j], __fadd_rn(ks, kc));
        float f = floorf(fabsf(m) * 100.0f);
        g_tok[b * 256 + j] = ((int)f) % VV;
    }
}

// ---------------------------------------------------------------------------
// Final: friend split-K reduce + linear [128,14] + softmax
// ---------------------------------------------------------------------------
__global__ void final_kernel(const float* __restrict__ f1b,
                             const float* __restrict__ w2,
                             const float* __restrict__ b2,
                             float* __restrict__ out) {
    int b = blockIdx.x, tid = threadIdx.x;      // 128 threads
    __shared__ float sz[128];
    __shared__ float sl[14];
    __shared__ float red[2];
    {
        float ks = 0.f, kc = 0.f;
        const float* p = g_part + (size_t)b * NJ + tid;
#pragma unroll 8
        for (int k = 0; k < KSPLIT; k++) kadd(ks, kc, p[(size_t)k * BB * NJ]);
        sz[tid] = __fadd_rn(f1b[tid], __fadd_rn(ks, kc));
    }
    __syncthreads();
    if (tid < VV) {
        float a = b2[tid];
#pragma unroll 4
        for (int j = 0; j < 128; j++) a += sz[j] * w2[j * VV + tid];
        sl[tid] = a;
    }
    __syncthreads();
    if (tid == 0) {
        float mx = sl[0];
        for (int v = 1; v < VV; v++) mx = fmaxf(mx, sl[v]);
        float ssum = 0.f;
        for (int v = 0; v < VV; v++) ssum += expf(sl[v] - mx);
        red[0] = mx; red[1] = ssum;
    }
    __syncthreads();
    if (tid < VV)
        out[b * VV + tid] = expf(sl[tid] - red[0]) / red[1];
}

// ---------------------------------------------------------------------------
// Launch sequence — gemm is launch #4 (the ncu-captured slot)
// ---------------------------------------------------------------------------
extern "C" void kernel_launch(void* const* d_in, const int* in_sizes, int n_in,
                              void* d_out, int out_size) {
    const int*   x    = (const int*)  d_in[0];
    const float* eemb = (const float*)d_in[1];
    const float* ecw  = (const float*)d_in[2];
    const float* ecb  = (const float*)d_in[3];
    // d_in[4] = elw
    const float* elw  = (const float*)d_in[4];
    const float* elb  = (const float*)d_in[5];
    // d_in[6] rand_proj: provably unused (greedy loop output == arange)
    const float* mcw  = (const float*)d_in[7];
    const float* mcb  = (const float*)d_in[8];
    const float* mlw  = (const float*)d_in[9];
    const float* mlb  = (const float*)d_in[10];
    const float* femb = (const float*)d_in[11];
    const float* fcw  = (const float*)d_in[12];
    const float* fcb  = (const float*)d_in[13];
    const float* f1w  = (const float*)d_in[14];
    const float* f1b  = (const float*)d_in[15];
    const float* f2w  = (const float*)d_in[16];
    const float* f2b  = (const float*)d_in[17];
    float* out = (float*)d_out;

    static int attr_done = 0;
    if (!attr_done) {
        cudaFuncSetAttribute(gemm_kernel,
                             cudaFuncAttributeMaxDynamicSharedMemorySize,
                             GEMM_SMEM);
        attr_done = 1;
    }

    // ---- enemy branch (gemm = 4th launch -> profiled)
    me_kernel<<<NP, EMBD>>>(eemb, 0);
    wt_kernel<<<256, 256>>>(ecw, x, 0);
    G_kernel<<<dim3(14, 3, 2), 128>>>(0);
    gemm_kernel<<<KSPLIT, 512, GEMM_SMEM>>>(ecb, elw);

    // ---- manipulator
    prep2_kernel<<<96, 256>>>(mcw, mlw);
    manip_kernel<<<BB, 256>>>(elb, mcb, mlb);

    // ---- friend branch
    me_kernel<<<NP, EMBD>>>(femb, 1);
    wt_kernel<<<256, 256>>>(fcw, x, 1);
    G_kernel<<<dim3(14, 3, 2), 128>>>(1);
    gemm_kernel<<<KSPLIT, 512, GEMM_SMEM>>>(fcb, f1w);

    // ---- final projection + softmax
    final_kernel<<<BB, 128>>>(f1b, f2w, f2b, out);
}

// round 7
// speedup vs baseline: 1.1551x; 1.1551x over previous
#include <cuda_runtime.h>
#include <cstdint>

typedef unsigned long long ull;

// ---------------------------------------------------------------------------
// Shapes
// ---------------------------------------------------------------------------
#define BB    256
#define LL    256
#define HH    128
#define VV    14
#define NP    196
#define EMBD  512
#define OC    256
#define NJ    128
#define ZROW  (3*NP)
#define GSZ   ((3*NP + 1) * OC)         // per-slot G size (incl. zero row)
#define WTSZ  (3 * EMBD * OC)           // per-slot Wt size
// GEMM: grid 128 (one pooled h per block), 512 threads
#define KSPLIT 128
#define GKT    16
#define NSTG   16                        // KC = 256 = OC

// gemm dynamic smem
#define YS_BYTES  (2 * 256 * 18 * 8)     // ull Ys2[2][256][18] = 73728
#define WS_OFF    YS_BYTES
#define WS_BUF_B  (16 * 128 * 4)         // 8192 per buffer
#define GEMM_SMEM (YS_BYTES + 2 * WS_BUF_B)   // 90112

// ---------------------------------------------------------------------------
// Scratch
// ---------------------------------------------------------------------------
__device__ float g_ME[2 * NP * EMBD];
__device__ float g_Wt[2 * WTSZ];
__device__ float g_G[2 * GSZ];
__device__ int   g_Ppad[BB * 130];               // pair ids, idx = h'+1
__device__ float g_Yp[(size_t)HH * BB * OC];     // Y, layout [h][m][o] (32MB)
__device__ float g_part[(size_t)KSPLIT * BB * NJ];
__device__ float g_MW[3 * 64 * 128];
__device__ float g_A[3 * 64 * 256];

// ---------------------------------------------------------------------------
// helpers
// ---------------------------------------------------------------------------
__device__ __forceinline__ ull pk2(float x, float y) {
    ull r; asm("mov.b64 %0, {%1,%2};" : "=l"(r) : "f"(x), "f"(y)); return r;
}
__device__ __forceinline__ ull fma2(ull a, ull b, ull c) {
    ull d; asm("fma.rn.f32x2 %0, %1, %2, %3;" : "=l"(d) : "l"(a), "l"(b), "l"(c));
    return d;
}
__device__ __forceinline__ void upk2(ull v, float& x, float& y) {
    asm("mov.b64 {%0,%1}, %2;" : "=f"(x), "=f"(y) : "l"(v));
}
__device__ __forceinline__ void kadd(float& s, float& c, float x) {
    float y = __fadd_rn(x, -c);
    float t = __fadd_rn(s, y);
    c = __fadd_rn(__fadd_rn(t, -s), -y);
    s = t;
}
__device__ __forceinline__ void cpa16(uint32_t d, const float* s) {
    asm volatile("cp.async.cg.shared.global [%0], [%1], 16;" :: "r"(d), "l"(s));
}
__device__ __forceinline__ void cpa_commit() {
    asm volatile("cp.async.commit_group;" ::);
}
__device__ __forceinline__ void cpa_wait0() {
    asm volatile("cp.async.wait_group 0;" ::);
}

// ---------------------------------------------------------------------------
// prep_all: me (both slots) + wt (both slots, + enemy Ppad + zero rows) + prep2
// 1392 blocks x 256 threads, branch by block range.
// ---------------------------------------------------------------------------
__global__ void __launch_bounds__(256) prep_all(const float* __restrict__ eemb,
                                                const float* __restrict__ femb,
                                                const float* __restrict__ ecw,
                                                const float* __restrict__ fcw,
                                                const int*   __restrict__ x,
                                                const float* __restrict__ mcw,
                                                const float* __restrict__ mlw) {
    __shared__ float sw[4608];
    int bid = blockIdx.x, tid = threadIdx.x;
    if (bid < 784) {                                  // me: pair-max embeddings
        int slot = bid >= 392;
        int q = bid - slot * 392;
        int p = q >> 1, c = (q & 1) * 256 + tid;
        const float* emb = slot ? femb : eemb;
        int t0 = p / VV, t1 = p % VV;
        g_ME[slot * NP * EMBD + p * EMBD + c] =
            fmaxf(emb[t0 * EMBD + c], emb[t1 * EMBD + c]);
    } else if (bid < 1296) {                          // wt: conv slice transpose
        int idx = bid - 784;
        int slot = idx >= 256;
        int o = idx & 255;
        const float* w = slot ? fcw : ecw;
#pragma unroll
        for (int i = 0; i < 18; i++)
            sw[i * 256 + tid] = w[(size_t)o * 4608 + i * 256 + tid];
        __syncthreads();
        float* Wt = g_Wt + slot * WTSZ;
        for (int i = tid; i < 1536; i += 256) {
            int c = i & 511, kh = i >> 9;
            Wt[(kh * EMBD + c) * OC + o] = sw[c * 9 + kh * 3 + 1];
        }
        if (o == 0) g_G[slot * GSZ + ZROW * OC + tid] = 0.f;
        if (slot == 0) {                              // enemy pair-id table
            int b = o;
            const int* tb = x + b * LL;
            if (tid < 130) {
                int hp = tid - 1;
                int p = -1;
                if (hp >= 0 && hp < HH) p = tb[2 * hp] * VV + tb[2 * hp + 1];
                g_Ppad[b * 130 + tid] = p;
            }
        }
    } else {                                          // prep2: manip weights
        int blk = bid - 1296;
        if (blk < 32) {
            int idx = blk * 256 + tid;                // 8192
            int base = idx * 9 + 1;
            float w0 = mcw[base], w1 = mcw[base + 3], w2 = mcw[base + 6];
            g_MW[0 * 8192 + idx] = w1 + w2;
            g_MW[1 * 8192 + idx] = w0 + w1 + w2;
            g_MW[2 * 8192 + idx] = w0 + w1;
        } else {
            int o = blk - 32;                         // 0..63
            int j = tid;
            const float* base = mlw + (size_t)(o * 128) * 256 + j;
            g_A[0 * 16384 + o * 256 + j] = base[0];
            g_A[2 * 16384 + o * 256 + j] = base[127 * 256];
            float s0 = 0, c0 = 0, s1 = 0, c1 = 0, s2 = 0, c2 = 0, s3 = 0, c3 = 0;
#pragma unroll 4
            for (int h = 1; h < 32; h++)   kadd(s0, c0, base[h * 256]);
#pragma unroll 4
            for (int h = 32; h < 64; h++)  kadd(s1, c1, base[h * 256]);
#pragma unroll 4
            for (int h = 64; h < 96; h++)  kadd(s2, c2, base[h * 256]);
#pragma unroll 4
            for (int h = 96; h < 127; h++) kadd(s3, c3, base[h * 256]);
            g_A[1 * 16384 + o * 256 + j] =
                __fadd_rn(__fadd_rn(__fadd_rn(s0, c0), __fadd_rn(s1, c1)),
                          __fadd_rn(__fadd_rn(s2, c2), __fadd_rn(s3, c3)));
        }
    }
}

// ---------------------------------------------------------------------------
// G_all: G[slot][kh][p][o] = sum_c ME[slot][p][c] * Wt[slot][kh][c][o]
// grid (14, 3, 4): z = oz + 2*slot. Unroll-8 prefetch on Wt loads (MLP 8).
// ---------------------------------------------------------------------------
__global__ void __launch_bounds__(128) G_all() {
    int pg = blockIdx.x;
    int kh = blockIdx.y;
    int oz = blockIdx.z & 1, slot = blockIdx.z >> 1;
    int o = oz * 128 + threadIdx.x;
    int t = threadIdx.x;
    __shared__ ull sME2[7][128];
    ull acc[7];
#pragma unroll
    for (int i = 0; i < 7; i++) acc[i] = 0ull;
    const float* ME = g_ME + slot * NP * EMBD;
    const float* Wt = g_Wt + slot * WTSZ;
    for (int cc = 0; cc < EMBD; cc += 128) {
#pragma unroll
        for (int i = 0; i < 7; i++)
            sME2[i][t] = pk2(ME[(pg * 14 + 2 * i) * EMBD + cc + t],
                             ME[(pg * 14 + 2 * i + 1) * EMBD + cc + t]);
        __syncthreads();
#pragma unroll 1
        for (int c8 = 0; c8 < 128; c8 += 8) {
            float wv[8];
#pragma unroll
            for (int u = 0; u < 8; u++)
                wv[u] = Wt[(kh * EMBD + cc + c8 + u) * OC + o];
#pragma unroll
            for (int u = 0; u < 8; u++) {
                ull pw = pk2(wv[u], wv[u]);
#pragma unroll
                for (int i = 0; i < 7; i++)
                    acc[i] = fma2(pw, sME2[i][c8 + u], acc[i]);
            }
        }
        __syncthreads();
    }
    float* G = g_G + slot * GSZ;
#pragma unroll
    for (int i = 0; i < 7; i++) {
        float lo, hi; upk2(acc[i], lo, hi);
        G[(kh * NP + pg * 14 + 2 * i) * OC + o]     = lo;
        G[(kh * NP + pg * 14 + 2 * i + 1) * OC + o] = hi;
    }
}

// ---------------------------------------------------------------------------
// Y_kernel: Y[h][m][o] = cb[o] + G0[p(h-1)] + G1[p(h)] + G2[p(h+1)]
// grid (128, 64), 256 threads = 4 m-rows x 64 o4-threads.
// ---------------------------------------------------------------------------
__global__ void __launch_bounds__(256) Y_kernel(const float* __restrict__ cb,
                                                int slot) {
    int h = blockIdx.x;
    int m = blockIdx.y * 4 + (threadIdx.x >> 6);
    int o = (threadIdx.x & 63) * 4;
    const int* Pr = g_Ppad + m * 130;
    int pm = Pr[h];                       // pair at h-1
    int p0 = Pr[h + 1];                   // pair at h
    int pp = Pr[h + 2];                   // pair at h+1
    const float* G = g_G + slot * GSZ;
    int r0 = (pm < 0) ? ZROW : (0 * NP + pm);
    int r1 = 1 * NP + p0;
    int r2 = (pp < 0) ? ZROW : (2 * NP + pp);
    const float4 g0 = *(const float4*)&G[r0 * OC + o];
    const float4 g1 = *(const float4*)&G[r1 * OC + o];
    const float4 g2 = *(const float4*)&G[r2 * OC + o];
    const float4 bi = *(const float4*)&cb[o];
    float4 vy;
    vy.x = bi.x + g0.x + g1.x + g2.x;
    vy.y = bi.y + g0.y + g1.y + g2.y;
    vy.z = bi.z + g0.z + g1.z + g2.z;
    vy.w = bi.w + g0.w + g1.w + g2.w;
    *(float4*)&g_Yp[((size_t)h * BB + m) * OC + o] = vy;
}

// ---------------------------------------------------------------------------
// GEMM: partial C over one pooled h. Pure streamer: Y via LDG.128->pk2->STS,
// W via cp.async; double-buffered; 8m x (4x2n) FFMA2 thread tile.
// ---------------------------------------------------------------------------
__global__ void __launch_bounds__(512) gemm_kernel(const float* __restrict__ Wl) {
    extern __shared__ char sm[];
    ull   (*Ys2)[256][18] = (ull(*)[256][18])sm;
    float (*Ws)[16][128]  = (float(*)[16][128])(sm + WS_OFF);

    int h = blockIdx.x, tid = threadIdx.x;
    const float* Yb = g_Yp + (size_t)h * BB * OC;

    int wkk = tid >> 5, wc4 = (tid & 31) * 4;
    uint32_t wdst = (uint32_t)__cvta_generic_to_shared(&Ws[0][wkk][wc4]);
    int ym = tid >> 2, yk4 = (tid & 3) * 4;           // rows ym, ym+128
    int nt = tid & 15, mt = tid >> 4, m0 = mt * 8;

    float4 vy[2];

    // preload stage 0
    vy[0] = *(const float4*)&Yb[(size_t)ym * OC + yk4];
    vy[1] = *(const float4*)&Yb[(size_t)(ym + 128) * OC + yk4];
    cpa16(wdst, &Wl[((size_t)wkk * HH + h) * NJ + wc4]);
    cpa_commit();
#pragma unroll
    for (int i = 0; i < 2; i++) {
        int m = ym + i * 128;
        ulonglong2 a; a.x = pk2(vy[i].x, vy[i].x); a.y = pk2(vy[i].y, vy[i].y);
        ulonglong2 b; b.x = pk2(vy[i].z, vy[i].z); b.y = pk2(vy[i].w, vy[i].w);
        *(ulonglong2*)&Ys2[0][m][yk4]     = a;
        *(ulonglong2*)&Ys2[0][m][yk4 + 2] = b;
    }
    cpa_wait0();
    __syncthreads();

    ull acc[8][4];
#pragma unroll
    for (int i = 0; i < 8; i++)
#pragma unroll
        for (int k = 0; k < 4; k++) acc[i][k] = 0ull;

#pragma unroll 1
    for (int s = 0; s < NSTG; s++) {
        int buf = s & 1;
        if (s + 1 < NSTG) {
            vy[0] = *(const float4*)&Yb[(size_t)ym * OC + (s + 1) * 16 + yk4];
            vy[1] = *(const float4*)&Yb[(size_t)(ym + 128) * OC + (s + 1) * 16 + yk4];
            cpa16(wdst + (buf ^ 1) * WS_BUF_B,
                  &Wl[((size_t)((s + 1) * 16 + wkk) * HH + h) * NJ + wc4]);
            cpa_commit();
        }
#pragma unroll
        for (int kk = 0; kk < GKT; kk++) {
            ull bb[4];
#pragma unroll
            for (int k = 0; k < 4; k++)
                bb[k] = *(const ull*)&Ws[buf][kk][nt * 2 + k * 32];
#pragma unroll
            for (int i = 0; i < 8; i++) {
                ull ya = Ys2[buf][m0 + i][kk];
#pragma unroll
                for (int k = 0; k < 4; k++)
                    acc[i][k] = fma2(ya, bb[k], acc[i][k]);
            }
        }
        if (s + 1 < NSTG) {
            int nb = buf ^ 1;
#pragma unroll
            for (int i = 0; i < 2; i++) {
                int m = ym + i * 128;
                ulonglong2 a; a.x = pk2(vy[i].x, vy[i].x); a.y = pk2(vy[i].y, vy[i].y);
                ulonglong2 b; b.x = pk2(vy[i].z, vy[i].z); b.y = pk2(vy[i].w, vy[i].w);
                *(ulonglong2*)&Ys2[nb][m][yk4]     = a;
                *(ulonglong2*)&Ys2[nb][m][yk4 + 2] = b;
            }
            cpa_wait0();
        }
        __syncthreads();
    }

    float* P = g_part + (size_t)h * BB * NJ;
#pragma unroll
    for (int i = 0; i < 8; i++)
#pragma unroll
        for (int k = 0; k < 4; k++)
            *(ull*)&P[(size_t)(m0 + i) * NJ + nt * 2 + k * 32] = acc[i][k];
}

// ---------------------------------------------------------------------------
// Manipulator: split-K reduce + softmax + collapsed conv/linear + tokens
// + friend pair-id table (from this block's tokens).
// ---------------------------------------------------------------------------
__global__ void __launch_bounds__(256) manip_kernel(const float* __restrict__ elb,
                                                    const float* __restrict__ mcb,
                                                    const float* __restrict__ mlb) {
    int b = blockIdx.x, tid = threadIdx.x;
    __shared__ float seo[128];
    __shared__ float sr[192];
    __shared__ float s[128];
    __shared__ int   stok[256];
    float v = 0.f;
    if (tid < 128) {                                   // split-K reduce, 4 Kahan chains
        float s0 = 0, c0 = 0, s1 = 0, c1 = 0, s2 = 0, c2 = 0, s3 = 0, c3 = 0;
        const float* p = g_part + (size_t)b * NJ + tid;
#pragma unroll 8
        for (int k = 0; k < KSPLIT; k += 4) {
            kadd(s0, c0, p[(size_t)k * BB * NJ]);
            kadd(s1, c1, p[(size_t)(k + 1) * BB * NJ]);
            kadd(s2, c2, p[(size_t)(k + 2) * BB * NJ]);
            kadd(s3, c3, p[(size_t)(k + 3) * BB * NJ]);
        }
        v = __fadd_rn(elb[tid],
            __fadd_rn(__fadd_rn(__fadd_rn(s0, c0), __fadd_rn(s1, c1)),
                      __fadd_rn(__fadd_rn(s2, c2), __fadd_rn(s3, c3))));
        s[tid] = v;
    }
    __syncthreads();
    for (int st = 64; st > 0; st >>= 1) {
        if (tid < st) s[tid] = fmaxf(s[tid], s[tid + st]);
        __syncthreads();
    }
    float mx = s[0];
    __syncthreads();
    float e = 0.f;
    if (tid < 128) { e = expf(v - mx); s[tid] = e; }
    __syncthreads();
    for (int st = 64; st > 0; st >>= 1) {
        if (tid < st) s[tid] += s[tid + st];
        __syncthreads();
    }
    if (tid < 128) seo[tid] = e / s[0];
    __syncthreads();
    if (tid < 192) {                                   // conv-row dots, 4 chains
        int o = tid % 64;
        const float* Wr = g_MW + (tid / 64) * 8192 + o * 128;
        float s0 = 0, c0 = 0, s1 = 0, c1 = 0, s2 = 0, c2 = 0, s3 = 0, c3 = 0;
#pragma unroll 8
        for (int c = 0; c < 128; c += 4) {
            kadd(s0, c0, __fmul_rn(seo[c],     Wr[c]));
            kadd(s1, c1, __fmul_rn(seo[c + 1], Wr[c + 1]));
            kadd(s2, c2, __fmul_rn(seo[c + 2], Wr[c + 2]));
            kadd(s3, c3, __fmul_rn(seo[c + 3], Wr[c + 3]));
        }
        float a = __fadd_rn(__fadd_rn(__fadd_rn(s0, c0), __fadd_rn(s1, c1)),
                            __fadd_rn(__fadd_rn(s2, c2), __fadd_rn(s3, c3)));
        sr[tid] = fmaxf(__fadd_rn(mcb[o], a), 0.f);
    }
    __syncthreads();
    {                                                  // reduced linear, 4 chains
        int j = tid;
        float s0 = 0, c0 = 0, s1 = 0, c1 = 0, s2 = 0, c2 = 0, s3 = 0, c3 = 0;
#pragma unroll 8
        for (int q = 0; q < 192; q += 4) {
            kadd(s0, c0, __fmul_rn(sr[q],     g_A[q * 256 + j]));
            kadd(s1, c1, __fmul_rn(sr[q + 1], g_A[(q + 1) * 256 + j]));
            kadd(s2, c2, __fmul_rn(sr[q + 2], g_A[(q + 2) * 256 + j]));
            kadd(s3, c3, __fmul_rn(sr[q + 3], g_A[(q + 3) * 256 + j]));
        }
        float a = __fadd_rn(__fadd_rn(__fadd_rn(s0, c0), __fadd_rn(s1, c1)),
                            __fadd_rn(__fadd_rn(s2, c2), __fadd_rn(s3, c3)));
        float m = __fadd_rn(mlb[j], a);
        stok[tid] = ((int)floorf(fabsf(m) * 100.0f)) % VV;
    }
    __syncthreads();
    if (tid < 130) {                                   // friend pair-id table
        int hp = tid - 1;
        int p = -1;
        if (hp >= 0 && hp < HH) p = stok[2 * hp] * VV + stok[2 * hp + 1];
        g_Ppad[b * 130 + tid] = p;
    }
}

// ---------------------------------------------------------------------------
// Final: friend split-K reduce + linear [128,14] + softmax over 14
// ---------------------------------------------------------------------------
__global__ void final_kernel(const float* __restrict__ f1b,
                             const float* __restrict__ w2,
                             const float* __restrict__ b2,
                             float* __restrict__ out) {
    int b = blockIdx.x, tid = threadIdx.x;            // 128 threads
    __shared__ float sz[128];
    __shared__ float sl[14];
    __shared__ float red[2];
    {
        float a0 = 0, a1 = 0, a2 = 0, a3 = 0;
        const float* p = g_part + (size_t)b * NJ + tid;
#pragma unroll 8
        for (int k = 0; k < KSPLIT; k += 4) {
            a0 += p[(size_t)k * BB * NJ];
            a1 += p[(size_t)(k + 1) * BB * NJ];
            a2 += p[(size_t)(k + 2) * BB * NJ];
            a3 += p[(size_t)(k + 3) * BB * NJ];
        }
        sz[tid] = f1b[tid] + ((a0 + a1) + (a2 + a3));
    }
    __syncthreads();
    if (tid < VV) {
        float a = b2[tid];
#pragma unroll 4
        for (int j = 0; j < 128; j++) a += sz[j] * w2[j * VV + tid];
        sl[tid] = a;
    }
    __syncthreads();
    if (tid == 0) {
        float mx = sl[0];
        for (int v = 1; v < VV; v++) mx = fmaxf(mx, sl[v]);
        float ssum = 0.f;
        for (int v = 0; v < VV; v++) ssum += expf(sl[v] - mx);
        red[0] = mx; red[1] = ssum;
    }
    __syncthreads();
    if (tid < VV)
        out[b * VV + tid] = expf(sl[tid] - red[0]) / red[1];
}

// ---------------------------------------------------------------------------
// Launch sequence — 8 launches, gemm is #4 (profiled slot)
// ---------------------------------------------------------------------------
extern "C" void kernel_launch(void* const* d_in, const int* in_sizes, int n_in,
                              void* d_out, int out_size) {
    const int*   x    = (const int*)  d_in[0];
    const float* eemb = (const float*)d_in[1];
    const float* ecw  = (const float*)d_in[2];
    const float* ecb  = (const float*)d_in[3];
    const float* elw  = (const float*)d_in[4];
    const float* elb  = (const float*)d_in[5];
    // d_in[6] rand_proj: provably unused (greedy loop output == arange)
    const float* mcw  = (const float*)d_in[7];
    const float* mcb  = (const float*)d_in[8];
    const float* mlw  = (const float*)d_in[9];
    const float* mlb  = (const float*)d_in[10];
    const float* femb = (const float*)d_in[11];
    const float* fcw  = (const float*)d_in[12];
    const float* fcb  = (const float*)d_in[13];
    const float* f1w  = (const float*)d_in[14];
    const float* f1b  = (const float*)d_in[15];
    const float* f2w  = (const float*)d_in[16];
    const float* f2b  = (const float*)d_in[17];
    float* out = (float*)d_out;

    // unconditional: deterministic, call-count independent, capture-safe
    cudaFuncSetAttribute(gemm_kernel,
                         cudaFuncAttributeMaxDynamicSharedMemorySize,
                         GEMM_SMEM);

    prep_all<<<1392, 256>>>(eemb, femb, ecw, fcw, x, mcw, mlw);
    G_all<<<dim3(14, 3, 4), 128>>>();
    Y_kernel<<<dim3(HH, 64), 256>>>(ecb, 0);
    gemm_kernel<<<KSPLIT, 512, GEMM_SMEM>>>(elw);          // profiled slot
    manip_kernel<<<BB, 256>>>(elb, mcb, mlb);
    Y_kernel<<<dim3(HH, 64), 256>>>(fcb, 1);
    gemm_kernel<<<KSPLIT, 512, GEMM_SMEM>>>(f1w);
    final_kernel<<<BB, 128>>>(f1b, f2w, f2b, out);
}

// round 8
// speedup vs baseline: 1.2402x; 1.0736x over previous
#include <cuda_runtime.h>
#include <cstdint>

typedef unsigned long long ull;

// ---------------------------------------------------------------------------
// Shapes
// ---------------------------------------------------------------------------
#define BB    256
#define LL    256
#define HH    128
#define VV    14
#define NP    196
#define EMBD  512
#define OC    256
#define NJ    128
#define ZROW  (3*NP)
#define GSZ   ((3*NP + 1) * OC)
#define WTSZ  (3 * EMBD * OC)
// GEMM: grid (2 m-halves x 128 h) = 256 blocks x 256 threads, 2 blocks/SM
#define KSPLIT 128
#define GKT    32
#define NSTG   8                          // KC = 256 = OC
#define YPAD   36                         // 144B row stride (16B-aligned)

// gemm dynamic smem
#define YS_BYTES  (2 * 128 * YPAD * 4)    // float Ys[2][128][36] = 36864
#define WS_OFF    YS_BYTES
#define WS_BUF_B  (GKT * 128 * 4)         // 16384 per buffer
#define GEMM_SMEM (YS_BYTES + 2 * WS_BUF_B)   // 69632

// prep_all dynamic smem (wt-transpose section)
#define PREP_SMEM (256 * 73 * 4)          // 74752

// ---------------------------------------------------------------------------
// Scratch
// ---------------------------------------------------------------------------
__device__ float g_ME[2 * NP * EMBD];
__device__ float g_Wt[2 * WTSZ];                 // [slot][kh][c][o]
__device__ float g_G[2 * GSZ];
__device__ int   g_Ppad[BB * 130];               // pair ids, idx = h'+1
__device__ float g_Yp[(size_t)HH * BB * OC];     // Y, layout [h][m][o]
__device__ float g_part[(size_t)KSPLIT * BB * NJ];
__device__ float g_MW[3 * 64 * 128];
__device__ float g_A[3 * 64 * 256];

// ---------------------------------------------------------------------------
// helpers
// ---------------------------------------------------------------------------
__device__ __forceinline__ ull pk2(float x, float y) {
    ull r; asm("mov.b64 %0, {%1,%2};" : "=l"(r) : "f"(x), "f"(y)); return r;
}
__device__ __forceinline__ ull fma2(ull a, ull b, ull c) {
    ull d; asm("fma.rn.f32x2 %0, %1, %2, %3;" : "=l"(d) : "l"(a), "l"(b), "l"(c));
    return d;
}
__device__ __forceinline__ void upk2(ull v, float& x, float& y) {
    asm("mov.b64 {%0,%1}, %2;" : "=f"(x), "=f"(y) : "l"(v));
}
__device__ __forceinline__ void kadd(float& s, float& c, float x) {
    float y = __fadd_rn(x, -c);
    float t = __fadd_rn(s, y);
    c = __fadd_rn(__fadd_rn(t, -s), -y);
    s = t;
}
__device__ __forceinline__ void cpa16(uint32_t d, const float* s) {
    asm volatile("cp.async.cg.shared.global [%0], [%1], 16;" :: "r"(d), "l"(s));
}
__device__ __forceinline__ void cpa_commit() {
    asm volatile("cp.async.commit_group;" ::);
}
__device__ __forceinline__ void cpa_wait0() {
    asm volatile("cp.async.wait_group 0;" ::);
}

// ---------------------------------------------------------------------------
// prep_all (dynamic smem 74.75KB):
//   [0,784)    me: pair-max embeddings, both slots
//   [784,912)  wt: coalesced smem transpose -> g_Wt[slot][kh][c][o]
//   [912,1008) prep2: manip weight collapse + prefix sums
//   [1008,1040) ppad: enemy pair-id table (+ zero G rows)
// ---------------------------------------------------------------------------
__global__ void __launch_bounds__(256) prep_all(const float* __restrict__ eemb,
                                                const float* __restrict__ femb,
                                                const float* __restrict__ ecw,
                                                const float* __restrict__ fcw,
                                                const int*   __restrict__ x,
                                                const float* __restrict__ mcw,
                                                const float* __restrict__ mlw) {
    extern __shared__ float sw2[];                // [256][73]
    int bid = blockIdx.x, tid = threadIdx.x;
    if (bid < 784) {                              // --- me
        int slot = bid >= 392;
        int q = bid - slot * 392;
        int p = q >> 1, c = (q & 1) * 256 + tid;
        const float* emb = slot ? femb : eemb;
        int t0 = p / VV, t1 = p % VV;
        g_ME[slot * NP * EMBD + p * EMBD + c] =
            fmaxf(emb[t0 * EMBD + c], emb[t1 * EMBD + c]);
    } else if (bid < 912) {                       // --- wt transpose
        int idx = bid - 784;
        int slot = idx >> 6;
        int cb_ = (idx & 63) * 8;                 // c-chunk base (8 c's)
        const float* w = slot ? fcw : ecw;
        // read 72 contiguous floats per o (this thread's o = tid)
        const float4* src = (const float4*)&w[(size_t)tid * 4608 + cb_ * 9];
#pragma unroll
        for (int i = 0; i < 18; i++) {
            float4 v = src[i];
            sw2[tid * 73 + i * 4 + 0] = v.x;
            sw2[tid * 73 + i * 4 + 1] = v.y;
            sw2[tid * 73 + i * 4 + 2] = v.z;
            sw2[tid * 73 + i * 4 + 3] = v.w;
        }
        __syncthreads();
        float* Wt = g_Wt + slot * WTSZ;
#pragma unroll
        for (int j = 0; j < 24; j++) {            // 3 kh x 8 c rows
            int kh = j >> 3, c = cb_ + (j & 7);
            Wt[(kh * EMBD + c) * OC + tid] =
                sw2[tid * 73 + (j & 7) * 9 + kh * 3 + 1];
        }
    } else if (bid < 1008) {                      // --- prep2
        int blk = bid - 912;
        if (blk < 32) {
            int idx = blk * 256 + tid;            // 8192
            int base = idx * 9 + 1;
            float w0 = mcw[base], w1 = mcw[base + 3], w2 = mcw[base + 6];
            g_MW[0 * 8192 + idx] = w1 + w2;
            g_MW[1 * 8192 + idx] = w0 + w1 + w2;
            g_MW[2 * 8192 + idx] = w0 + w1;
        } else {
            int o = blk - 32;                     // 0..63
            int j = tid;
            const float* base = mlw + (size_t)(o * 128) * 256 + j;
            g_A[0 * 16384 + o * 256 + j] = base[0];
            g_A[2 * 16384 + o * 256 + j] = base[127 * 256];
            float s0 = 0, c0 = 0, s1 = 0, c1 = 0, s2 = 0, c2 = 0, s3 = 0, c3 = 0;
#pragma unroll 4
            for (int h = 1; h < 32; h++)   kadd(s0, c0, base[h * 256]);
#pragma unroll 4
            for (int h = 32; h < 64; h++)  kadd(s1, c1, base[h * 256]);
#pragma unroll 4
            for (int h = 64; h < 96; h++)  kadd(s2, c2, base[h * 256]);
#pragma unroll 4
            for (int h = 96; h < 127; h++) kadd(s3, c3, base[h * 256]);
            g_A[1 * 16384 + o * 256 + j] =
                __fadd_rn(__fadd_rn(__fadd_rn(s0, c0), __fadd_rn(s1, c1)),
                          __fadd_rn(__fadd_rn(s2, c2), __fadd_rn(s3, c3)));
        }
    } else {                                      // --- ppad (+ zero rows)
        int pblk = bid - 1008;                    // 0..31
        int b = pblk * 8 + (tid >> 5);
        int lane = tid & 31;
        const int* tb = x + b * LL;
#pragma unroll
        for (int r = 0; r < 5; r++) {
            int idx = r * 32 + lane;
            if (idx < 130) {
                int hp = idx - 1;
                int p = -1;
                if (hp >= 0 && hp < HH) p = tb[2 * hp] * VV + tb[2 * hp + 1];
                g_Ppad[b * 130 + idx] = p;
            }
        }
        if (pblk < 2) g_G[pblk * GSZ + ZROW * OC + tid] = 0.f;
    }
}

// ---------------------------------------------------------------------------
// G_all: G[slot][kh][p][o] = sum_c ME[slot][p][c] * Wt[slot][kh][c][o]
// grid (14, 3, 4): z = oz + 2*slot. Unroll-8 prefetch on Wt loads.
// ---------------------------------------------------------------------------
__global__ void __launch_bounds__(128) G_all() {
    int pg = blockIdx.x;
    int kh = blockIdx.y;
    int oz = blockIdx.z & 1, slot = blockIdx.z >> 1;
    int o = oz * 128 + threadIdx.x;
    int t = threadIdx.x;
    __shared__ ull sME2[7][128];
    ull acc[7];
#pragma unroll
    for (int i = 0; i < 7; i++) acc[i] = 0ull;
    const float* ME = g_ME + slot * NP * EMBD;
    const float* Wt = g_Wt + slot * WTSZ;
    for (int cc = 0; cc < EMBD; cc += 128) {
#pragma unroll
        for (int i = 0; i < 7; i++)
            sME2[i][t] = pk2(ME[(pg * 14 + 2 * i) * EMBD + cc + t],
                             ME[(pg * 14 + 2 * i + 1) * EMBD + cc + t]);
        __syncthreads();
#pragma unroll 1
        for (int c8 = 0; c8 < 128; c8 += 8) {
            float wv[8];
#pragma unroll
            for (int u = 0; u < 8; u++)
                wv[u] = Wt[(kh * EMBD + cc + c8 + u) * OC + o];
#pragma unroll
            for (int u = 0; u < 8; u++) {
                ull pw = pk2(wv[u], wv[u]);
#pragma unroll
                for (int i = 0; i < 7; i++)
                    acc[i] = fma2(pw, sME2[i][c8 + u], acc[i]);
            }
        }
        __syncthreads();
    }
    float* G = g_G + slot * GSZ;
#pragma unroll
    for (int i = 0; i < 7; i++) {
        float lo, hi; upk2(acc[i], lo, hi);
        G[(kh * NP + pg * 14 + 2 * i) * OC + o]     = lo;
        G[(kh * NP + pg * 14 + 2 * i + 1) * OC + o] = hi;
    }
}

// ---------------------------------------------------------------------------
// Y_kernel: Y[h][m][o] = cb[o] + G0[p(h-1)] + G1[p(h)] + G2[p(h+1)]
// ---------------------------------------------------------------------------
__global__ void __launch_bounds__(256) Y_kernel(const float* __restrict__ cb,
                                                int slot) {
    int h = blockIdx.x;
    int m = blockIdx.y * 4 + (threadIdx.x >> 6);
    int o = (threadIdx.x & 63) * 4;
    const int* Pr = g_Ppad + m * 130;
    int pm = Pr[h];
    int p0 = Pr[h + 1];
    int pp = Pr[h + 2];
    const float* G = g_G + slot * GSZ;
    int r0 = (pm < 0) ? ZROW : (0 * NP + pm);
    int r1 = 1 * NP + p0;
    int r2 = (pp < 0) ? ZROW : (2 * NP + pp);
    const float4 g0 = *(const float4*)&G[r0 * OC + o];
    const float4 g1 = *(const float4*)&G[r1 * OC + o];
    const float4 g2 = *(const float4*)&G[r2 * OC + o];
    const float4 bi = *(const float4*)&cb[o];
    float4 vy;
    vy.x = bi.x + g0.x + g1.x + g2.x;
    vy.y = bi.y + g0.y + g1.y + g2.y;
    vy.z = bi.z + g0.z + g1.z + g2.z;
    vy.w = bi.w + g0.w + g1.w + g2.w;
    *(float4*)&g_Yp[((size_t)h * BB + m) * OC + o] = vy;
}

// ---------------------------------------------------------------------------
// GEMM: block (mb, h) computes partial C[128,128] over k = one pooled h.
// 256 threads, 2 blocks/SM; Y + W tiles via cp.async, double-buffered;
// 8m x (4x2n) FFMA2 thread tile with pk2 in inner loop (alu pipe).
// ---------------------------------------------------------------------------
__global__ void __launch_bounds__(256, 2) gemm_kernel(const float* __restrict__ Wl) {
    extern __shared__ char sm[];
    float (*Ys)[128][YPAD] = (float(*)[128][YPAD])sm;
    float (*Ws)[GKT][128]  = (float(*)[GKT][128])(sm + WS_OFF);

    int mb = blockIdx.x, h = blockIdx.y;
    int tid = threadIdx.x;
    const float* Yb = g_Yp + ((size_t)h * BB + mb * 128) * OC;

    // staging coords: Y tile 128x32 = 1024 f4 (4/thread), W tile 32x128 same
    int yr[4], yc[4], wkk[4], wc[4];
#pragma unroll
    for (int i = 0; i < 4; i++) {
        int q = i * 256 + tid;
        yr[i] = q >> 3;  yc[i] = (q & 7) * 4;
        wkk[i] = q >> 5; wc[i] = (q & 31) * 4;
    }
    int nt = tid & 15, mt = tid >> 4, m0 = mt * 8;

    // stage 0
#pragma unroll
    for (int i = 0; i < 4; i++) {
        cpa16((uint32_t)__cvta_generic_to_shared(&Ys[0][yr[i]][yc[i]]),
              &Yb[(size_t)yr[i] * OC + yc[i]]);
        cpa16((uint32_t)__cvta_generic_to_shared(&Ws[0][wkk[i]][wc[i]]),
              &Wl[((size_t)wkk[i] * HH + h) * NJ + wc[i]]);
    }
    cpa_commit();
    cpa_wait0();
    __syncthreads();

    ull acc[8][4];
#pragma unroll
    for (int i = 0; i < 8; i++)
#pragma unroll
        for (int k = 0; k < 4; k++) acc[i][k] = 0ull;

#pragma unroll 1
    for (int s = 0; s < NSTG; s++) {
        int buf = s & 1;
        if (s + 1 < NSTG) {
            int nb = buf ^ 1;
            int k0 = (s + 1) * GKT;
#pragma unroll
            for (int i = 0; i < 4; i++) {
                cpa16((uint32_t)__cvta_generic_to_shared(&Ys[nb][yr[i]][yc[i]]),
                      &Yb[(size_t)yr[i] * OC + k0 + yc[i]]);
                cpa16((uint32_t)__cvta_generic_to_shared(&Ws[nb][wkk[i]][wc[i]]),
                      &Wl[((size_t)(k0 + wkk[i]) * HH + h) * NJ + wc[i]]);
            }
            cpa_commit();
        }
#pragma unroll
        for (int kk = 0; kk < GKT; kk++) {
            ull bb[4];
#pragma unroll
            for (int k = 0; k < 4; k++)
                bb[k] = *(const ull*)&Ws[buf][kk][nt * 2 + k * 32];
#pragma unroll
            for (int i = 0; i < 8; i++) {
                float a = Ys[buf][m0 + i][kk];
                ull pa = pk2(a, a);
#pragma unroll
                for (int k = 0; k < 4; k++)
                    acc[i][k] = fma2(pa, bb[k], acc[i][k]);
            }
        }
        if (s + 1 < NSTG) cpa_wait0();
        __syncthreads();
    }

    float* P = g_part + ((size_t)h * BB + mb * 128) * NJ;
#pragma unroll
    for (int i = 0; i < 8; i++)
#pragma unroll
        for (int k = 0; k < 4; k++)
            *(ull*)&P[(size_t)(m0 + i) * NJ + nt * 2 + k * 32] = acc[i][k];
}

// ---------------------------------------------------------------------------
// Manipulator: split-K reduce (8 Kahan chains) + softmax + collapsed
// conv/linear + tokens + friend pair-id table.
// ---------------------------------------------------------------------------
__global__ void __launch_bounds__(256) manip_kernel(const float* __restrict__ elb,
                                                    const float* __restrict__ mcb,
                                                    const float* __restrict__ mlb) {
    int b = blockIdx.x, tid = threadIdx.x;
    __shared__ float seo[128];
    __shared__ float sr[192];
    __shared__ float s[128];
    __shared__ int   stok[256];
    float v = 0.f;
    if (tid < 128) {
        float ss[8], cc8[8];
#pragma unroll
        for (int u = 0; u < 8; u++) { ss[u] = 0.f; cc8[u] = 0.f; }
        const float* p = g_part + (size_t)b * NJ + tid;
#pragma unroll 2
        for (int k = 0; k < KSPLIT; k += 8)
#pragma unroll
            for (int u = 0; u < 8; u++)
                kadd(ss[u], cc8[u], p[(size_t)(k + u) * BB * NJ]);
        float t01 = __fadd_rn(__fadd_rn(ss[0], cc8[0]), __fadd_rn(ss[1], cc8[1]));
        float t23 = __fadd_rn(__fadd_rn(ss[2], cc8[2]), __fadd_rn(ss[3], cc8[3]));
        float t45 = __fadd_rn(__fadd_rn(ss[4], cc8[4]), __fadd_rn(ss[5], cc8[5]));
        float t67 = __fadd_rn(__fadd_rn(ss[6], cc8[6]), __fadd_rn(ss[7], cc8[7]));
        v = __fadd_rn(elb[tid],
                      __fadd_rn(__fadd_rn(t01, t23), __fadd_rn(t45, t67)));
        s[tid] = v;
    }
    __syncthreads();
    for (int st = 64; st > 0; st >>= 1) {
        if (tid < st) s[tid] = fmaxf(s[tid], s[tid + st]);
        __syncthreads();
    }
    float mx = s[0];
    __syncthreads();
    float e = 0.f;
    if (tid < 128) { e = expf(v - mx); s[tid] = e; }
    __syncthreads();
    for (int st = 64; st > 0; st >>= 1) {
        if (tid < st) s[tid] += s[tid + st];
        __syncthreads();
    }
    if (tid < 128) seo[tid] = e / s[0];
    __syncthreads();
    if (tid < 192) {
        int o = tid % 64;
        const float* Wr = g_MW + (tid / 64) * 8192 + o * 128;
        float s0 = 0, c0 = 0, s1 = 0, c1 = 0, s2 = 0, c2 = 0, s3 = 0, c3 = 0;
#pragma unroll 8
        for (int c = 0; c < 128; c += 4) {
            kadd(s0, c0, __fmul_rn(seo[c],     Wr[c]));
            kadd(s1, c1, __fmul_rn(seo[c + 1], Wr[c + 1]));
            kadd(s2, c2, __fmul_rn(seo[c + 2], Wr[c + 2]));
            kadd(s3, c3, __fmul_rn(seo[c + 3], Wr[c + 3]));
        }
        float a = __fadd_rn(__fadd_rn(__fadd_rn(s0, c0), __fadd_rn(s1, c1)),
                            __fadd_rn(__fadd_rn(s2, c2), __fadd_rn(s3, c3)));
        sr[tid] = fmaxf(__fadd_rn(mcb[o], a), 0.f);
    }
    __syncthreads();
    {
        int j = tid;
        float s0 = 0, c0 = 0, s1 = 0, c1 = 0, s2 = 0, c2 = 0, s3 = 0, c3 = 0;
#pragma unroll 8
        for (int q = 0; q < 192; q += 4) {
            kadd(s0, c0, __fmul_rn(sr[q],     g_A[q * 256 + j]));
            kadd(s1, c1, __fmul_rn(sr[q + 1], g_A[(q + 1) * 256 + j]));
            kadd(s2, c2, __fmul_rn(sr[q + 2], g_A[(q + 2) * 256 + j]));
            kadd(s3, c3, __fmul_rn(sr[q + 3], g_A[(q + 3) * 256 + j]));
        }
        float a = __fadd_rn(__fadd_rn(__fadd_rn(s0, c0), __fadd_rn(s1, c1)),
                            __fadd_rn(__fadd_rn(s2, c2), __fadd_rn(s3, c3)));
        float m = __fadd_rn(mlb[j], a);
        stok[tid] = ((int)floorf(fabsf(m) * 100.0f)) % VV;
    }
    __syncthreads();
    if (tid < 130) {
        int hp = tid - 1;
        int p = -1;
        if (hp >= 0 && hp < HH) p = stok[2 * hp] * VV + stok[2 * hp + 1];
        g_Ppad[b * 130 + tid] = p;
    }
}

// ---------------------------------------------------------------------------
// Final: friend split-K reduce (8 accs) + linear [128,14] + softmax
// ---------------------------------------------------------------------------
__global__ void final_kernel(const float* __restrict__ f1b,
                             const float* __restrict__ w2,
                             const float* __restrict__ b2,
                             float* __restrict__ out) {
    int b = blockIdx.x, tid = threadIdx.x;            // 128 threads
    __shared__ float sz[128];
    __shared__ float sl[14];
    __shared__ float red[2];
    {
        float a[8];
#pragma unroll
        for (int u = 0; u < 8; u++) a[u] = 0.f;
        const float* p = g_part + (size_t)b * NJ + tid;
#pragma unroll 2
        for (int k = 0; k < KSPLIT; k += 8)
#pragma unroll
            for (int u = 0; u < 8; u++) a[u] += p[(size_t)(k + u) * BB * NJ];
        sz[tid] = f1b[tid] + (((a[0] + a[1]) + (a[2] + a[3])) +
                              ((a[4] + a[5]) + (a[6] + a[7])));
    }
    __syncthreads();
    if (tid < VV) {
        float a = b2[tid];
#pragma unroll 4
        for (int j = 0; j < 128; j++) a += sz[j] * w2[j * VV + tid];
        sl[tid] = a;
    }
    __syncthreads();
    if (tid == 0) {
        float mx = sl[0];
        for (int v = 1; v < VV; v++) mx = fmaxf(mx, sl[v]);
        float ssum = 0.f;
        for (int v = 0; v < VV; v++) ssum += expf(sl[v] - mx);
        red[0] = mx; red[1] = ssum;
    }
    __syncthreads();
    if (tid < VV)
        out[b * VV + tid] = expf(sl[tid] - red[0]) / red[1];
}

// ---------------------------------------------------------------------------
// Launch sequence — 8 launches, gemm is #4 (profiled slot)
// ---------------------------------------------------------------------------
extern "C" void kernel_launch(void* const* d_in, const int* in_sizes, int n_in,
                              void* d_out, int out_size) {
    const int*   x    = (const int*)  d_in[0];
    const float* eemb = (const float*)d_in[1];
    const float* ecw  = (const float*)d_in[2];
    const float* ecb  = (const float*)d_in[3];
    const float* elw  = (const float*)d_in[4];
    const float* elb  = (const float*)d_in[5];
    // d_in[6] rand_proj: provably unused (greedy loop output == arange)
    const float* mcw  = (const float*)d_in[7];
    const float* mcb  = (const float*)d_in[8];
    const float* mlw  = (const float*)d_in[9];
    const float* mlb  = (const float*)d_in[10];
    const float* femb = (const float*)d_in[11];
    const float* fcw  = (const float*)d_in[12];
    const float* fcb  = (const float*)d_in[13];
    const float* f1w  = (const float*)d_in[14];
    const float* f1b  = (const float*)d_in[15];
    const float* f2w  = (const float*)d_in[16];
    const float* f2b  = (const float*)d_in[17];
    float* out = (float*)d_out;

    cudaFuncSetAttribute(gemm_kernel,
                         cudaFuncAttributeMaxDynamicSharedMemorySize, GEMM_SMEM);
    cudaFuncSetAttribute(prep_all,
                         cudaFuncAttributeMaxDynamicSharedMemorySize, PREP_SMEM);

    prep_all<<<1040, 256, PREP_SMEM>>>(eemb, femb, ecw, fcw, x, mcw, mlw);
    G_all<<<dim3(14, 3, 4), 128>>>();
    Y_kernel<<<dim3(HH, 64), 256>>>(ecb, 0);
    gemm_kernel<<<dim3(2, HH), 256, GEMM_SMEM>>>(elw);     // profiled slot
    manip_kernel<<<BB, 256>>>(elb, mcb, mlb);
    Y_kernel<<<dim3(HH, 64), 256>>>(fcb, 1);
    gemm_kernel<<<dim3(2, HH), 256, GEMM_SMEM>>>(f1w);
    final_kernel<<<BB, 128>>>(f1b, f2w, f2b, out);
}

// round 9
// speedup vs baseline: 1.4623x; 1.1791x over previous
#include <cuda_runtime.h>
#include <cstdint>

typedef unsigned long long ull;

// ---------------------------------------------------------------------------
// Shapes
// ---------------------------------------------------------------------------
#define BB    256
#define LL    256
#define HH    128
#define VV    14
#define NP    196
#define EMBD  512
#define OC    256
#define NJ    128
#define ZROW  (3*NP)
#define GSZ   ((3*NP + 1) * OC)
#define WTSZ  (3 * EMBD * OC)
// GEMM: grid (2 m-halves x 128 h) = 256 blocks x 256 threads, 2 blocks/SM
#define KSPLIT 128
#define GKT    32
#define NSTG   8                          // KC = 256 = OC
#define YT_STRIDE 132                     // 528B rows: 16B-aligned, 4-way STS ok

// gemm dynamic smem
#define YT_BYTES  (2 * GKT * YT_STRIDE * 4)   // 33792
#define WS_OFF    YT_BYTES
#define WS_BUF_B  (GKT * 128 * 4)             // 16384
#define GEMM_SMEM (YT_BYTES + 2 * WS_BUF_B)   // 66560

// ---------------------------------------------------------------------------
// Scratch
// ---------------------------------------------------------------------------
__device__ float g_ME[2 * NP * EMBD];
__device__ float g_Wt[2 * WTSZ];                 // [slot][kh][c][o]
__device__ float g_G[2 * GSZ];
__device__ int   g_Ppad[BB * 130];               // pair ids, idx = h'+1
__device__ float g_Yp[(size_t)HH * BB * OC];     // Y, layout [h][m][o]
__device__ float g_part[(size_t)BB * KSPLIT * NJ];   // [m][k][j]
__device__ float g_MW[3 * 64 * 128];
__device__ float g_A[3 * 64 * 256];
__device__ float g_Apart[8 * 64 * 256];          // A prefix partials [chunk][o][j]

// ---------------------------------------------------------------------------
// helpers
// ---------------------------------------------------------------------------
__device__ __forceinline__ ull pk2(float x, float y) {
    ull r; asm("mov.b64 %0, {%1,%2};" : "=l"(r) : "f"(x), "f"(y)); return r;
}
__device__ __forceinline__ ull fma2(ull a, ull b, ull c) {
    ull d; asm("fma.rn.f32x2 %0, %1, %2, %3;" : "=l"(d) : "l"(a), "l"(b), "l"(c));
    return d;
}
__device__ __forceinline__ void upk2(ull v, float& x, float& y) {
    asm("mov.b64 {%0,%1}, %2;" : "=f"(x), "=f"(y) : "l"(v));
}
__device__ __forceinline__ void kadd(float& s, float& c, float x) {
    float y = __fadd_rn(x, -c);
    float t = __fadd_rn(s, y);
    c = __fadd_rn(__fadd_rn(t, -s), -y);
    s = t;
}
__device__ __forceinline__ void cpa16(uint32_t d, const float* s) {
    asm volatile("cp.async.cg.shared.global [%0], [%1], 16;" :: "r"(d), "l"(s));
}
__device__ __forceinline__ void cpa_commit() {
    asm volatile("cp.async.commit_group;" ::);
}
__device__ __forceinline__ void cpa_wait0() {
    asm volatile("cp.async.wait_group 0;" ::);
}

// ---------------------------------------------------------------------------
// prep_all (no smem):
//   [0,784)      me: pair-max embeddings (both slots)
//   [784,1040)   wt: conv kw=1 slice -> g_Wt[slot][kh][c][o] (register select)
//   [1040,1072)  mw: manip conv weight collapse
//   [1072,1584)  Apart: reduced-linear prefix partials (8 h-chunks)
//   [1584,1616)  ppad: enemy pair-id table + zero G rows
// ---------------------------------------------------------------------------
__global__ void __launch_bounds__(256) prep_all(const float* __restrict__ eemb,
                                                const float* __restrict__ femb,
                                                const float* __restrict__ ecw,
                                                const float* __restrict__ fcw,
                                                const int*   __restrict__ x,
                                                const float* __restrict__ mcw,
                                                const float* __restrict__ mlw) {
    int bid = blockIdx.x, tid = threadIdx.x;
    if (bid < 784) {                              // --- me
        int slot = bid >= 392;
        int q = bid - slot * 392;
        int p = q >> 1, c = (q & 1) * 256 + tid;
        const float* emb = slot ? femb : eemb;
        int t0 = p / VV, t1 = p % VV;
        g_ME[slot * NP * EMBD + p * EMBD + c] =
            fmaxf(emb[t0 * EMBD + c], emb[t1 * EMBD + c]);
    } else if (bid < 1040) {                      // --- wt (no smem, no sync)
        int idx = bid - 784;
        int slot = idx >> 7;
        int cb_ = (idx & 127) * 4;                // 4 c's per block
        const float* w = slot ? fcw : ecw;
        // 36 contiguous floats per o (= tid): rows c..c+3, 9 taps each
        const float4* src = (const float4*)&w[(size_t)tid * 4608 + cb_ * 9];
        float4 v0 = src[0], v1 = src[1], v2 = src[2], v3 = src[3], v4 = src[4],
               v5 = src[5], v6 = src[6], v7 = src[7], v8 = src[8];
        // tap index cloc*9 + kh*3 + 1
        float taps[12] = {v0.y, v1.x, v1.w,   // cloc 0: kh 0,1,2
                          v2.z, v3.y, v4.x,   // cloc 1
                          v4.w, v5.z, v6.y,   // cloc 2
                          v7.x, v7.w, v8.z};  // cloc 3
        float* Wt = g_Wt + slot * WTSZ;
#pragma unroll
        for (int cl = 0; cl < 4; cl++)
#pragma unroll
            for (int kh = 0; kh < 3; kh++)
                Wt[(kh * EMBD + cb_ + cl) * OC + tid] = taps[cl * 3 + kh];
    } else if (bid < 1072) {                      // --- mw
        int idx = (bid - 1040) * 256 + tid;       // 8192
        int base = idx * 9 + 1;
        float w0 = mcw[base], w1 = mcw[base + 3], w2 = mcw[base + 6];
        g_MW[0 * 8192 + idx] = w1 + w2;
        g_MW[1 * 8192 + idx] = w0 + w1 + w2;
        g_MW[2 * 8192 + idx] = w0 + w1;
    } else if (bid < 1584) {                      // --- Apart
        int blk2 = bid - 1072;                    // 0..511
        int c = blk2 >> 6;                        // h-chunk 0..7
        int o = blk2 & 63;
        int j = tid;
        const float* base = mlw + (size_t)(o * 128) * 256 + j;
        if (c == 0) {
            g_A[0 * 16384 + o * 256 + j] = base[0];
            g_A[2 * 16384 + o * 256 + j] = base[127 * 256];
        }
        int h0 = 1 + c * 16;
        int h1 = (c == 7) ? 127 : h0 + 16;        // exclusive
        float s0 = 0, c0 = 0, s1 = 0, c1 = 0;
        int h = h0;
        for (; h + 1 < h1; h += 2) {
            kadd(s0, c0, base[h * 256]);
            kadd(s1, c1, base[(h + 1) * 256]);
        }
        if (h < h1) kadd(s0, c0, base[h * 256]);
        g_Apart[c * 16384 + o * 256 + j] =
            __fadd_rn(__fadd_rn(s0, c0), __fadd_rn(s1, c1));
    } else {                                      // --- ppad (+ zero rows)
        int pblk = bid - 1584;                    // 0..31
        int b = pblk * 8 + (tid >> 5);
        int lane = tid & 31;
        const int* tb = x + b * LL;
#pragma unroll
        for (int r = 0; r < 5; r++) {
            int idx = r * 32 + lane;
            if (idx < 130) {
                int hp = idx - 1;
                int p = -1;
                if (hp >= 0 && hp < HH) p = tb[2 * hp] * VV + tb[2 * hp + 1];
                g_Ppad[b * 130 + idx] = p;
            }
        }
        if (pblk < 2) g_G[pblk * GSZ + ZROW * OC + tid] = 0.f;
    }
}

// ---------------------------------------------------------------------------
// G_all: pg<14: G[slot][kh][p][o] = sum_c ME[p][c]*Wt[kh][c][o] (FFMA2).
// pg==14: finalize g_A[1] from the 8 Apart chunks (fixed order).
// grid (15, 3, 4): z = oz + 2*slot.
// ---------------------------------------------------------------------------
__global__ void __launch_bounds__(128) G_all() {
    int pg = blockIdx.x;
    int kh = blockIdx.y;
    int t = threadIdx.x;
    if (pg == 14) {
        int lin = (kh * 4 + blockIdx.z) * 128 + t;     // 0..1535
        for (int e = lin; e < 16384; e += 1536) {
            float s = 0.f;
#pragma unroll
            for (int c = 0; c < 8; c++) s = __fadd_rn(s, g_Apart[c * 16384 + e]);
            g_A[1 * 16384 + e] = s;
        }
        return;
    }
    int oz = blockIdx.z & 1, slot = blockIdx.z >> 1;
    int o = oz * 128 + t;
    __shared__ ull sME2[7][128];
    ull acc[7];
#pragma unroll
    for (int i = 0; i < 7; i++) acc[i] = 0ull;
    const float* ME = g_ME + slot * NP * EMBD;
    const float* Wt = g_Wt + slot * WTSZ;
    for (int cc = 0; cc < EMBD; cc += 128) {
#pragma unroll
        for (int i = 0; i < 7; i++)
            sME2[i][t] = pk2(ME[(pg * 14 + 2 * i) * EMBD + cc + t],
                             ME[(pg * 14 + 2 * i + 1) * EMBD + cc + t]);
        __syncthreads();
#pragma unroll 1
        for (int c8 = 0; c8 < 128; c8 += 8) {
            float wv[8];
#pragma unroll
            for (int u = 0; u < 8; u++)
                wv[u] = Wt[(kh * EMBD + cc + c8 + u) * OC + o];
#pragma unroll
            for (int u = 0; u < 8; u++) {
                ull pw = pk2(wv[u], wv[u]);
#pragma unroll
                for (int i = 0; i < 7; i++)
                    acc[i] = fma2(pw, sME2[i][c8 + u], acc[i]);
            }
        }
        __syncthreads();
    }
    float* G = g_G + slot * GSZ;
#pragma unroll
    for (int i = 0; i < 7; i++) {
        float lo, hi; upk2(acc[i], lo, hi);
        G[(kh * NP + pg * 14 + 2 * i) * OC + o]     = lo;
        G[(kh * NP + pg * 14 + 2 * i + 1) * OC + o] = hi;
    }
}

// ---------------------------------------------------------------------------
// Y_kernel: Y[h][m][o] = cb[o] + G0[p(h-1)] + G1[p(h)] + G2[p(h+1)]
// ---------------------------------------------------------------------------
__global__ void __launch_bounds__(256) Y_kernel(const float* __restrict__ cb,
                                                int slot) {
    int h = blockIdx.x;
    int m = blockIdx.y * 4 + (threadIdx.x >> 6);
    int o = (threadIdx.x & 63) * 4;
    const int* Pr = g_Ppad + m * 130;
    int pm = Pr[h];
    int p0 = Pr[h + 1];
    int pp = Pr[h + 2];
    const float* G = g_G + slot * GSZ;
    int r0 = (pm < 0) ? ZROW : (0 * NP + pm);
    int r1 = 1 * NP + p0;
    int r2 = (pp < 0) ? ZROW : (2 * NP + pp);
    const float4 g0 = *(const float4*)&G[r0 * OC + o];
    const float4 g1 = *(const float4*)&G[r1 * OC + o];
    const float4 g2 = *(const float4*)&G[r2 * OC + o];
    const float4 bi = *(const float4*)&cb[o];
    float4 vy;
    vy.x = bi.x + g0.x + g1.x + g2.x;
    vy.y = bi.y + g0.y + g1.y + g2.y;
    vy.z = bi.z + g0.z + g1.z + g2.z;
    vy.w = bi.w + g0.w + g1.w + g2.w;
    *(float4*)&g_Yp[((size_t)h * BB + m) * OC + o] = vy;
}

// ---------------------------------------------------------------------------
// GEMM: block (mb, h) computes partial C[128,128] over k = one pooled h.
// Y tile staged TRANSPOSED (Yt[k][m]) so a-operands come via LDS.128;
// W via cp.async. 256 threads, 2 blocks/SM, 8m x (4x2n) FFMA2 tile.
// ---------------------------------------------------------------------------
__global__ void __launch_bounds__(256, 2) gemm_kernel(const float* __restrict__ Wl) {
    extern __shared__ char sm[];
    float (*Yt)[GKT][YT_STRIDE] = (float(*)[GKT][YT_STRIDE])sm;
    float (*Ws)[GKT][128]      = (float(*)[GKT][128])(sm + WS_OFF);

    int mb = blockIdx.x, h = blockIdx.y;
    int tid = threadIdx.x;
    const float* Yb = g_Yp + ((size_t)h * BB + mb * 128) * OC;

    int yr[4], yc[4], wkk[4], wc[4];
#pragma unroll
    for (int i = 0; i < 4; i++) {
        int q = i * 256 + tid;
        yr[i] = q >> 3;  yc[i] = (q & 7) * 4;
        wkk[i] = q >> 5; wc[i] = (q & 31) * 4;
    }
    int nt = tid & 15, mt = tid >> 4, m0 = mt * 8;

    float4 vy[4];
    // stage 0
#pragma unroll
    for (int i = 0; i < 4; i++)
        vy[i] = *(const float4*)&Yb[(size_t)yr[i] * OC + yc[i]];
#pragma unroll
    for (int i = 0; i < 4; i++)
        cpa16((uint32_t)__cvta_generic_to_shared(&Ws[0][wkk[i]][wc[i]]),
              &Wl[((size_t)wkk[i] * HH + h) * NJ + wc[i]]);
    cpa_commit();
#pragma unroll
    for (int i = 0; i < 4; i++) {
        Yt[0][yc[i] + 0][yr[i]] = vy[i].x;
        Yt[0][yc[i] + 1][yr[i]] = vy[i].y;
        Yt[0][yc[i] + 2][yr[i]] = vy[i].z;
        Yt[0][yc[i] + 3][yr[i]] = vy[i].w;
    }
    cpa_wait0();
    __syncthreads();

    ull acc[8][4];
#pragma unroll
    for (int i = 0; i < 8; i++)
#pragma unroll
        for (int k = 0; k < 4; k++) acc[i][k] = 0ull;

#pragma unroll 1
    for (int s = 0; s < NSTG; s++) {
        int buf = s & 1;
        if (s + 1 < NSTG) {
            int k0 = (s + 1) * GKT;
            int nb = buf ^ 1;
#pragma unroll
            for (int i = 0; i < 4; i++)
                vy[i] = *(const float4*)&Yb[(size_t)yr[i] * OC + k0 + yc[i]];
#pragma unroll
            for (int i = 0; i < 4; i++)
                cpa16((uint32_t)__cvta_generic_to_shared(&Ws[nb][wkk[i]][wc[i]]),
                      &Wl[((size_t)(k0 + wkk[i]) * HH + h) * NJ + wc[i]]);
            cpa_commit();
        }
#pragma unroll
        for (int kk = 0; kk < GKT; kk++) {
            float4 a0 = *(const float4*)&Yt[buf][kk][m0];
            float4 a1 = *(const float4*)&Yt[buf][kk][m0 + 4];
            ull bb[4];
#pragma unroll
            for (int k = 0; k < 4; k++)
                bb[k] = *(const ull*)&Ws[buf][kk][nt * 2 + k * 32];
            float av[8] = {a0.x, a0.y, a0.z, a0.w, a1.x, a1.y, a1.z, a1.w};
#pragma unroll
            for (int i = 0; i < 8; i++) {
                ull pa = pk2(av[i], av[i]);
#pragma unroll
                for (int k = 0; k < 4; k++)
                    acc[i][k] = fma2(pa, bb[k], acc[i][k]);
            }
        }
        if (s + 1 < NSTG) {
            int nb = buf ^ 1;
#pragma unroll
            for (int i = 0; i < 4; i++) {
                Yt[nb][yc[i] + 0][yr[i]] = vy[i].x;
                Yt[nb][yc[i] + 1][yr[i]] = vy[i].y;
                Yt[nb][yc[i] + 2][yr[i]] = vy[i].z;
                Yt[nb][yc[i] + 3][yr[i]] = vy[i].w;
            }
            cpa_wait0();
        }
        __syncthreads();
    }

    // epilogue: g_part layout [m][k][j]
#pragma unroll
    for (int i = 0; i < 8; i++) {
        float* P = g_part + ((size_t)(mb * 128 + m0 + i) * KSPLIT + h) * NJ;
#pragma unroll
        for (int k = 0; k < 4; k++)
            *(ull*)&P[nt * 2 + k * 32] = acc[i][k];
    }
}

// ---------------------------------------------------------------------------
// Manipulator: coalesced split-K reduce (2 k-halves x 8 Kahan chains)
// + softmax + collapsed conv/linear + tokens + friend pair-id table.
// ---------------------------------------------------------------------------
__global__ void __launch_bounds__(256) manip_kernel(const float* __restrict__ elb,
                                                    const float* __restrict__ mcb,
                                                    const float* __restrict__ mlb) {
    int b = blockIdx.x, tid = threadIdx.x;
    __shared__ float sh2[2][128];
    __shared__ float seo[128];
    __shared__ float sr[192];
    __shared__ float s[128];
    __shared__ int   stok[256];
    {   // split-K reduce: g_part[b][k][j], contiguous 64KB per b
        int jj = tid & 127, kh2 = tid >> 7;
        const float* p = g_part + (size_t)b * (KSPLIT * NJ) + (size_t)kh2 * 64 * NJ + jj;
        float ss[8], cc8[8];
#pragma unroll
        for (int u = 0; u < 8; u++) { ss[u] = 0.f; cc8[u] = 0.f; }
#pragma unroll 2
        for (int k = 0; k < 64; k += 8)
#pragma unroll
            for (int u = 0; u < 8; u++)
                kadd(ss[u], cc8[u], p[(size_t)(k + u) * NJ]);
        float t01 = __fadd_rn(__fadd_rn(ss[0], cc8[0]), __fadd_rn(ss[1], cc8[1]));
        float t23 = __fadd_rn(__fadd_rn(ss[2], cc8[2]), __fadd_rn(ss[3], cc8[3]));
        float t45 = __fadd_rn(__fadd_rn(ss[4], cc8[4]), __fadd_rn(ss[5], cc8[5]));
        float t67 = __fadd_rn(__fadd_rn(ss[6], cc8[6]), __fadd_rn(ss[7], cc8[7]));
        sh2[kh2][jj] = __fadd_rn(__fadd_rn(t01, t23), __fadd_rn(t45, t67));
    }
    __syncthreads();
    float v = 0.f;
    if (tid < 128) {
        v = __fadd_rn(elb[tid], __fadd_rn(sh2[0][tid], sh2[1][tid]));
        s[tid] = v;
    }
    __syncthreads();
    for (int st = 64; st > 0; st >>= 1) {
        if (tid < st) s[tid] = fmaxf(s[tid], s[tid + st]);
        __syncthreads();
    }
    float mx = s[0];
    __syncthreads();
    float e = 0.f;
    if (tid < 128) { e = expf(v - mx); s[tid] = e; }
    __syncthreads();
    for (int st = 64; st > 0; st >>= 1) {
        if (tid < st) s[tid] += s[tid + st];
        __syncthreads();
    }
    if (tid < 128) seo[tid] = e / s[0];
    __syncthreads();
    if (tid < 192) {
        int o = tid % 64;
        const float* Wr = g_MW + (tid / 64) * 8192 + o * 128;
        float s0 = 0, c0 = 0, s1 = 0, c1 = 0, s2 = 0, c2 = 0, s3 = 0, c3 = 0;
#pragma unroll 8
        for (int c = 0; c < 128; c += 4) {
            kadd(s0, c0, __fmul_rn(seo[c],     Wr[c]));
            kadd(s1, c1, __fmul_rn(seo[c + 1], Wr[c + 1]));
            kadd(s2, c2, __fmul_rn(seo[c + 2], Wr[c + 2]));
            kadd(s3, c3, __fmul_rn(seo[c + 3], Wr[c + 3]));
        }
        float a = __fadd_rn(__fadd_rn(__fadd_rn(s0, c0), __fadd_rn(s1, c1)),
                            __fadd_rn(__fadd_rn(s2, c2), __fadd_rn(s3, c3)));
        sr[tid] = fmaxf(__fadd_rn(mcb[o], a), 0.f);
    }
    __syncthreads();
    {
        int j = tid;
        float s0 = 0, c0 = 0, s1 = 0, c1 = 0, s2 = 0, c2 = 0, s3 = 0, c3 = 0;
#pragma unroll 8
        for (int q = 0; q < 192; q += 4) {
            kadd(s0, c0, __fmul_rn(sr[q],     g_A[q * 256 + j]));
            kadd(s1, c1, __fmul_rn(sr[q + 1], g_A[(q + 1) * 256 + j]));
            kadd(s2, c2, __fmul_rn(sr[q + 2], g_A[(q + 2) * 256 + j]));
            kadd(s3, c3, __fmul_rn(sr[q + 3], g_A[(q + 3) * 256 + j]));
        }
        float a = __fadd_rn(__fadd_rn(__fadd_rn(s0, c0), __fadd_rn(s1, c1)),
                            __fadd_rn(__fadd_rn(s2, c2), __fadd_rn(s3, c3)));
        float m = __fadd_rn(mlb[j], a);
        stok[tid] = ((int)floorf(fabsf(m) * 100.0f)) % VV;
    }
    __syncthreads();
    if (tid < 130) {
        int hp = tid - 1;
        int p = -1;
        if (hp >= 0 && hp < HH) p = stok[2 * hp] * VV + stok[2 * hp + 1];
        g_Ppad[b * 130 + tid] = p;
    }
}

// ---------------------------------------------------------------------------
// Final: coalesced friend split-K reduce + linear [128,14] + softmax
// ---------------------------------------------------------------------------
__global__ void __launch_bounds__(256) final_kernel(const float* __restrict__ f1b,
                                                    const float* __restrict__ w2,
                                                    const float* __restrict__ b2,
                                                    float* __restrict__ out) {
    int b = blockIdx.x, tid = threadIdx.x;
    __shared__ float sh2[2][128];
    __shared__ float sz[128];
    __shared__ float sl[14];
    __shared__ float red[2];
    {
        int jj = tid & 127, kh2 = tid >> 7;
        const float* p = g_part + (size_t)b * (KSPLIT * NJ) + (size_t)kh2 * 64 * NJ + jj;
        float a[8];
#pragma unroll
        for (int u = 0; u < 8; u++) a[u] = 0.f;
#pragma unroll 2
        for (int k = 0; k < 64; k += 8)
#pragma unroll
            for (int u = 0; u < 8; u++) a[u] += p[(size_t)(k + u) * NJ];
        sh2[kh2][jj] = ((a[0] + a[1]) + (a[2] + a[3])) +
                       ((a[4] + a[5]) + (a[6] + a[7]));
    }
    __syncthreads();
    if (tid < 128) sz[tid] = f1b[tid] + (sh2[0][tid] + sh2[1][tid]);
    __syncthreads();
    if (tid < VV) {
        float a = b2[tid];
#pragma unroll 4
        for (int j = 0; j < 128; j++) a += sz[j] * w2[j * VV + tid];
        sl[tid] = a;
    }
    __syncthreads();
    if (tid == 0) {
        float mx = sl[0];
        for (int v = 1; v < VV; v++) mx = fmaxf(mx, sl[v]);
        float ssum = 0.f;
        for (int v = 0; v < VV; v++) ssum += expf(sl[v] - mx);
        red[0] = mx; red[1] = ssum;
    }
    __syncthreads();
    if (tid < VV)
        out[b * VV + tid] = expf(sl[tid] - red[0]) / red[1];
}

// ---------------------------------------------------------------------------
// Launch sequence — 8 launches, gemm is #4 (profiled slot)
// ---------------------------------------------------------------------------
extern "C" void kernel_launch(void* const* d_in, const int* in_sizes, int n_in,
                              void* d_out, int out_size) {
    const int*   x    = (const int*)  d_in[0];
    const float* eemb = (const float*)d_in[1];
    const float* ecw  = (const float*)d_in[2];
    const float* ecb  = (const float*)d_in[3];
    const float* elw  = (const float*)d_in[4];
    const float* elb  = (const float*)d_in[5];
    // d_in[6] rand_proj: provably unused (greedy loop output == arange)
    const float* mcw  = (const float*)d_in[7];
    const float* mcb  = (const float*)d_in[8];
    const float* mlw  = (const float*)d_in[9];
    const float* mlb  = (const float*)d_in[10];
    const float* femb = (const float*)d_in[11];
    const float* fcw  = (const float*)d_in[12];
    const float* fcb  = (const float*)d_in[13];
    const float* f1w  = (const float*)d_in[14];
    const float* f1b  = (const float*)d_in[15];
    const float* f2w  = (const float*)d_in[16];
    const float* f2b  = (const float*)d_in[17];
    float* out = (float*)d_out;

    cudaFuncSetAttribute(gemm_kernel,
                         cudaFuncAttributeMaxDynamicSharedMemorySize, GEMM_SMEM);

    prep_all<<<1616, 256>>>(eemb, femb, ecw, fcw, x, mcw, mlw);
    G_all<<<dim3(15, 3, 4), 128>>>();
    Y_kernel<<<dim3(HH, 64), 256>>>(ecb, 0);
    gemm_kernel<<<dim3(2, HH), 256, GEMM_SMEM>>>(elw);     // profiled slot
    manip_kernel<<<BB, 256>>>(elb, mcb, mlb);
    Y_kernel<<<dim3(HH, 64), 256>>>(fcb, 1);
    gemm_kernel<<<dim3(2, HH), 256, GEMM_SMEM>>>(f1w);
    final_kernel<<<BB, 256>>>(f1b, f2w, f2b, out);
}